// round 1
// baseline (speedup 1.0000x reference)
#include <cuda_runtime.h>

#define MAXN 50000
#define NBLK 256

// Scratch (device globals; allocation-free per harness rules)
__device__ float    g_h[MAXN * 64];      // x @ W_gat        [N,64]
__device__ float    g_acc[MAXN * 64];    // aggregate accum  [N,64]
__device__ float    g_asrc[MAXN * 4];    // per-head src attn logits
__device__ float    g_adst[MAXN * 4];
__device__ unsigned g_menc[MAXN * 4];    // encoded per-dst max
__device__ float    g_denom[MAXN * 4];   // softmax denominator

__device__ __forceinline__ float leaky(float v) { return v > 0.f ? v : 0.2f * v; }

// Monotone float<->uint mapping for atomicMax on floats
__device__ __forceinline__ unsigned fenc(float f) {
    unsigned u = __float_as_uint(f);
    return (u & 0x80000000u) ? ~u : (u | 0x80000000u);
}
__device__ __forceinline__ float fdec(unsigned u) {
    return __uint_as_float((u & 0x80000000u) ? (u & 0x7fffffffu) : ~u);
}

// Vector reduction (sm_90+): 4 floats, one L2 atomic op
__device__ __forceinline__ void red4(float* p, float a, float b, float c, float d) {
    asm volatile("red.global.add.v4.f32 [%0], {%1,%2,%3,%4};"
                 :: "l"(p), "f"(a), "f"(b), "f"(c), "f"(d) : "memory");
}

// ---------------------------------------------------------------------------
// K1: out[n,64] = x[n,128] @ W[128,64] (+ optional bias b0+b1).
// CTA: 32 nodes, 256 threads. Thread = (warp ty -> 4 nodes) x (lane tx -> 2 cols).
// Node-group is warp-uniform -> x reads are smem broadcasts (conflict-free).
// writeAcc=0 -> g_h, writeAcc=1 -> g_acc (with b_gat+b_res folded in).
// ---------------------------------------------------------------------------
__global__ void k_gemm64(const float* __restrict__ x, const float* __restrict__ W,
                         const float* __restrict__ b0, const float* __restrict__ b1,
                         int writeAcc, int n) {
    __shared__ float Ws[128 * 64];   // 32 KB
    __shared__ float xs[32 * 128];   // 16 KB
    int tid = threadIdx.x;
    for (int i = tid; i < 128 * 64; i += NBLK) Ws[i] = W[i];
    int base = blockIdx.x * 32;
    const float4* x4 = (const float4*)x;
    for (int i = tid; i < 32 * 32; i += NBLK) {
        int node = i >> 5, kk = i & 31;
        float4 v = make_float4(0.f, 0.f, 0.f, 0.f);
        if (base + node < n) v = x4[(base + node) * 32 + kk];
        ((float4*)xs)[i] = v;
    }
    __syncthreads();

    int tx = tid & 31;   // col pair: 2*tx, 2*tx+1
    int ty = tid >> 5;   // warp id: nodes ty*4 .. ty*4+3
    float acc[4][2] = {};
    const float* xp = xs + ty * 4 * 128;
#pragma unroll 4
    for (int k = 0; k < 128; k++) {
        float2 w = ((const float2*)(Ws + k * 64))[tx];
#pragma unroll
        for (int i = 0; i < 4; i++) {
            float xv = xp[i * 128 + k];
            acc[i][0] += xv * w.x;
            acc[i][1] += xv * w.y;
        }
    }
    float bias0 = 0.f, bias1 = 0.f;
    if (writeAcc) {
        bias0 = b0[2 * tx] + b1[2 * tx];
        bias1 = b0[2 * tx + 1] + b1[2 * tx + 1];
    }
    float* out = writeAcc ? g_acc : g_h;
#pragma unroll
    for (int i = 0; i < 4; i++) {
        int node = base + ty * 4 + i;
        if (node < n)
            ((float2*)(out + node * 64))[tx] =
                make_float2(acc[i][0] + bias0, acc[i][1] + bias1);
    }
}

// ---------------------------------------------------------------------------
// K2: per-(node,head) attention logits a_src/a_dst; init max/denom buffers.
// ---------------------------------------------------------------------------
__global__ void k_attn(const float* __restrict__ att_s, const float* __restrict__ att_d, int n) {
    __shared__ float ss[64], sd[64];
    int tid = threadIdx.x;
    if (tid < 64) { ss[tid] = att_s[tid]; sd[tid] = att_d[tid]; }
    __syncthreads();
    int gid = blockIdx.x * NBLK + tid;
    if (gid >= n * 4) return;
    int node = gid >> 2, hd = gid & 3;
    const float4* hp = (const float4*)(g_h + node * 64 + hd * 16);
    float s = 0.f, d = 0.f;
#pragma unroll
    for (int j = 0; j < 4; j++) {
        float4 v = hp[j];
        int b = hd * 16 + j * 4;
        s += v.x * ss[b] + v.y * ss[b + 1] + v.z * ss[b + 2] + v.w * ss[b + 3];
        d += v.x * sd[b] + v.y * sd[b + 1] + v.z * sd[b + 2] + v.w * sd[b + 3];
    }
    g_asrc[gid] = s;
    g_adst[gid] = d;
    g_menc[gid] = 0u;      // encoded -inf (every dst has a self-loop, never decoded empty)
    g_denom[gid] = 0.f;
}

// ---------------------------------------------------------------------------
// K3: per-destination segment max (edges + virtual self-loop edges).
// ---------------------------------------------------------------------------
__global__ void k_max(const int* __restrict__ ei, int E, int n) {
    int i = blockIdx.x * NBLK + threadIdx.x;
    int tot = E + n;
    if (i >= tot) return;
    int s, d;
    if (i < E) { s = ei[i]; d = ei[E + i]; } else { s = d = i - E; }
    float4 as = ((const float4*)g_asrc)[s];
    float4 ad = ((const float4*)g_adst)[d];
    unsigned* mp = g_menc + d * 4;
    atomicMax(mp + 0, fenc(leaky(as.x + ad.x)));
    atomicMax(mp + 1, fenc(leaky(as.y + ad.y)));
    atomicMax(mp + 2, fenc(leaky(as.z + ad.z)));
    atomicMax(mp + 3, fenc(leaky(as.w + ad.w)));
}

// ---------------------------------------------------------------------------
// K4: softmax denominator via vector red.
// ---------------------------------------------------------------------------
__global__ void k_den(const int* __restrict__ ei, int E, int n) {
    int i = blockIdx.x * NBLK + threadIdx.x;
    int tot = E + n;
    if (i >= tot) return;
    int s, d;
    if (i < E) { s = ei[i]; d = ei[E + i]; } else { s = d = i - E; }
    float4 as = ((const float4*)g_asrc)[s];
    float4 ad = ((const float4*)g_adst)[d];
    uint4 me = ((const uint4*)g_menc)[d];
    float w0 = __expf(leaky(as.x + ad.x) - fdec(me.x));
    float w1 = __expf(leaky(as.y + ad.y) - fdec(me.y));
    float w2 = __expf(leaky(as.z + ad.z) - fdec(me.z));
    float w3 = __expf(leaky(as.w + ad.w) - fdec(me.w));
    red4(g_denom + d * 4, w0, w1, w2, w3);
}

// ---------------------------------------------------------------------------
// K5: message aggregation. 16 threads per edge; thread t owns float4 #t of
// the 64-float row (head = t>>2). Gather h[src], vector-red into acc[dst].
// ---------------------------------------------------------------------------
__global__ void k_agg(const int* __restrict__ ei, int E, int n) {
    int gid = blockIdx.x * NBLK + threadIdx.x;
    int tot = E + n;
    int eid = gid >> 4;
    if (eid >= tot) return;
    int t = gid & 15;
    int s, d;
    if (eid < E) { s = ei[eid]; d = ei[E + eid]; } else { s = d = eid - E; }
    int hd = t >> 2;
    float a   = g_asrc[s * 4 + hd] + g_adst[d * 4 + hd];
    float m   = fdec(g_menc[d * 4 + hd]);
    float den = g_denom[d * 4 + hd];
    float alpha = __expf(leaky(a) - m) / (den + 1e-16f);
    float4 hv = ((const float4*)g_h)[s * 16 + t];
    red4(g_acc + d * 64 + t * 4, alpha * hv.x, alpha * hv.y, alpha * hv.z, alpha * hv.w);
}

// ---------------------------------------------------------------------------
// K6: BN(eval) + ReLU + [64x10] classifier.
// ---------------------------------------------------------------------------
__global__ void k_out(const float* __restrict__ gamma, const float* __restrict__ beta,
                      const float* __restrict__ rmean, const float* __restrict__ rvar,
                      const float* __restrict__ Wc, const float* __restrict__ bc,
                      float* __restrict__ out, int n) {
    __shared__ float sS[64], sB[64], sW[640], sbc[10];
    int tid = threadIdx.x;
    if (tid < 64) {
        float sc = gamma[tid] * rsqrtf(rvar[tid] + 1e-5f);
        sS[tid] = sc;
        sB[tid] = beta[tid] - rmean[tid] * sc;
    }
    for (int i = tid; i < 640; i += NBLK) sW[i] = Wc[i];
    if (tid < 10) sbc[tid] = bc[tid];
    __syncthreads();
    int node = blockIdx.x * NBLK + tid;
    if (node >= n) return;
    float lg[10];
#pragma unroll
    for (int c = 0; c < 10; c++) lg[c] = sbc[c];
    const float4* ap = (const float4*)(g_acc + node * 64);
#pragma unroll
    for (int j = 0; j < 16; j++) {
        float4 v = ap[j];
        float vv[4] = {v.x, v.y, v.z, v.w};
#pragma unroll
        for (int e = 0; e < 4; e++) {
            int k = j * 4 + e;
            float hb = fmaxf(vv[e] * sS[k] + sB[k], 0.f);
#pragma unroll
            for (int c = 0; c < 10; c++) lg[c] += hb * sW[k * 10 + c];
        }
    }
#pragma unroll
    for (int c = 0; c < 10; c++) out[node * 10 + c] = lg[c];
}

extern "C" void kernel_launch(void* const* d_in, const int* in_sizes, int n_in,
                              void* d_out, int out_size) {
    const float* x     = (const float*)d_in[0];
    const int*   ei    = (const int*)d_in[1];
    const float* Wg    = (const float*)d_in[2];
    const float* att_s = (const float*)d_in[3];
    const float* att_d = (const float*)d_in[4];
    const float* bg    = (const float*)d_in[5];
    const float* Wr    = (const float*)d_in[6];
    const float* br    = (const float*)d_in[7];
    const float* gamma = (const float*)d_in[8];
    const float* beta  = (const float*)d_in[9];
    const float* rmean = (const float*)d_in[10];
    const float* rvar  = (const float*)d_in[11];
    const float* Wc    = (const float*)d_in[12];
    const float* bc    = (const float*)d_in[13];
    float* out = (float*)d_out;

    int n = in_sizes[0] / 128;
    int E = in_sizes[1] / 2;
    int tot = E + n;

    int gemm_blocks = (n + 31) / 32;
    k_gemm64<<<gemm_blocks, NBLK>>>(x, Wg, bg, br, 0, n);   // g_h = x @ W_gat
    k_gemm64<<<gemm_blocks, NBLK>>>(x, Wr, bg, br, 1, n);   // g_acc = x@W_res + b_gat + b_res

    int attn_blocks = (n * 4 + NBLK - 1) / NBLK;
    k_attn<<<attn_blocks, NBLK>>>(att_s, att_d, n);

    int edge_blocks = (tot + NBLK - 1) / NBLK;
    k_max<<<edge_blocks, NBLK>>>(ei, E, n);
    k_den<<<edge_blocks, NBLK>>>(ei, E, n);

    long long agg_threads = (long long)tot * 16;
    int agg_blocks = (int)((agg_threads + NBLK - 1) / NBLK);
    k_agg<<<agg_blocks, NBLK>>>(ei, E, n);

    int out_blocks = (n + NBLK - 1) / NBLK;
    k_out<<<out_blocks, NBLK>>>(gamma, beta, rmean, rvar, Wc, bc, out, n);
}

// round 2
// speedup vs baseline: 1.3909x; 1.3909x over previous
#include <cuda_runtime.h>

#define MAXN 50000
#define MAXE 1600000
#define NBLK 256

// ---------------- scratch (device globals; no allocation) ----------------
__device__ float g_h[MAXN * 64];      // x @ W_gat
__device__ float g_acc[MAXN * 64];    // x @ W_res + b_gat + b_res
__device__ float g_asrc[MAXN * 4];
__device__ float g_adst[MAXN * 4];
__device__ int   g_cnt[MAXN];         // in-degree
__device__ int   g_cur[MAXN];         // scatter cursors
__device__ int   g_off[MAXN];         // within-block exclusive scan of cnt
__device__ int   g_bsum[256];
__device__ int   g_boff[256];
__device__ int   g_srcs[MAXE];        // CSR: src ids grouped by dst

__device__ __forceinline__ float leaky(float v) { return v > 0.f ? v : 0.2f * v; }

// ---------------------------------------------------------------------------
// K0: zero histogram + cursors
// ---------------------------------------------------------------------------
__global__ void k_zero(int n) {
    int i = blockIdx.x * NBLK + threadIdx.x;
    if (i < n) { g_cnt[i] = 0; g_cur[i] = 0; }
}

// ---------------------------------------------------------------------------
// K1: out[n,64] = x[n,128] @ W[128,64].
// writeAcc=0 -> g_h, plus fused attention-logit epilogue (a_src/a_dst).
// writeAcc=1 -> g_acc with b_gat+b_res folded in.
// CTA: 32 nodes, 256 threads. lane tx -> 2 cols; warp ty -> 4 nodes.
// ---------------------------------------------------------------------------
__global__ void k_gemm64(const float* __restrict__ x, const float* __restrict__ W,
                         const float* __restrict__ b0, const float* __restrict__ b1,
                         const float* __restrict__ att_s, const float* __restrict__ att_d,
                         int writeAcc, int n) {
    __shared__ float Ws[128 * 64];
    __shared__ float xs[32 * 128];
    int tid = threadIdx.x;
    for (int i = tid; i < 128 * 64; i += NBLK) Ws[i] = W[i];
    int base = blockIdx.x * 32;
    const float4* x4 = (const float4*)x;
    for (int i = tid; i < 32 * 32; i += NBLK) {
        int node = i >> 5, kk = i & 31;
        float4 v = make_float4(0.f, 0.f, 0.f, 0.f);
        if (base + node < n) v = x4[(base + node) * 32 + kk];
        ((float4*)xs)[i] = v;
    }
    __syncthreads();

    int tx = tid & 31;
    int ty = tid >> 5;
    float acc[4][2] = {};
    const float* xp = xs + ty * 4 * 128;
#pragma unroll 4
    for (int k = 0; k < 128; k++) {
        float2 w = ((const float2*)(Ws + k * 64))[tx];
#pragma unroll
        for (int i = 0; i < 4; i++) {
            float xv = xp[i * 128 + k];
            acc[i][0] += xv * w.x;
            acc[i][1] += xv * w.y;
        }
    }

    if (writeAcc) {
        float bias0 = b0[2 * tx] + b1[2 * tx];
        float bias1 = b0[2 * tx + 1] + b1[2 * tx + 1];
#pragma unroll
        for (int i = 0; i < 4; i++) {
            int node = base + ty * 4 + i;
            if (node < n)
                ((float2*)(g_acc + node * 64))[tx] =
                    make_float2(acc[i][0] + bias0, acc[i][1] + bias1);
        }
    } else {
        float as0 = att_s[2 * tx], as1 = att_s[2 * tx + 1];
        float ad0 = att_d[2 * tx], ad1 = att_d[2 * tx + 1];
        int hd = tx >> 3;
#pragma unroll
        for (int i = 0; i < 4; i++) {
            int node = base + ty * 4 + i;
            float ps = acc[i][0] * as0 + acc[i][1] * as1;
            float pd = acc[i][0] * ad0 + acc[i][1] * ad1;
#pragma unroll
            for (int off = 4; off; off >>= 1) {
                ps += __shfl_xor_sync(0xffffffffu, ps, off);
                pd += __shfl_xor_sync(0xffffffffu, pd, off);
            }
            if (node < n) {
                ((float2*)(g_h + node * 64))[tx] = make_float2(acc[i][0], acc[i][1]);
                if ((tx & 7) == 0) {
                    g_asrc[node * 4 + hd] = ps;
                    g_adst[node * 4 + hd] = pd;
                }
            }
        }
    }
}

// ---------------------------------------------------------------------------
// K2: degree histogram
// ---------------------------------------------------------------------------
__global__ void k_hist(const int* __restrict__ ei, int E) {
    int i = blockIdx.x * NBLK + threadIdx.x;
    if (i < E) atomicAdd(&g_cnt[ei[E + i]], 1);
}

// K3a: per-block exclusive scan of cnt (256 per block)
__global__ void k_scan1(int n) {
    __shared__ int sh[NBLK];
    int t = threadIdx.x;
    int gid = blockIdx.x * NBLK + t;
    int v = (gid < n) ? g_cnt[gid] : 0;
    sh[t] = v;
    __syncthreads();
#pragma unroll
    for (int off = 1; off < NBLK; off <<= 1) {
        int xv = (t >= off) ? sh[t - off] : 0;
        __syncthreads();
        sh[t] += xv;
        __syncthreads();
    }
    if (gid < n) g_off[gid] = sh[t] - v;
    if (t == NBLK - 1) g_bsum[blockIdx.x] = sh[t];
}

// K3b: scan of block sums (single block)
__global__ void k_scan2(int nblocks) {
    __shared__ int sh[256];
    int t = threadIdx.x;
    int v = (t < nblocks) ? g_bsum[t] : 0;
    sh[t] = v;
    __syncthreads();
#pragma unroll
    for (int off = 1; off < 256; off <<= 1) {
        int xv = (t >= off) ? sh[t - off] : 0;
        __syncthreads();
        sh[t] += xv;
        __syncthreads();
    }
    g_boff[t] = sh[t] - v;
}

// K4: scatter src ids into CSR order
__global__ void k_scatter(const int* __restrict__ ei, int E) {
    int i = blockIdx.x * NBLK + threadIdx.x;
    if (i >= E) return;
    int s = ei[i], d = ei[E + i];
    int p = g_off[d] + g_boff[d >> 8] + atomicAdd(&g_cur[d], 1);
    g_srcs[p] = s;
}

// ---------------------------------------------------------------------------
// K5: warp-per-destination aggregation, fused with residual + BN + ReLU +
// classifier. Unnormalized softmax accumulation (no max pass needed: logits
// are O(1), exp cannot overflow; softmax is shift-invariant).
// Lane owns output cols 2l, 2l+1; head hd = l>>3.
// ---------------------------------------------------------------------------
__global__ void k_agg(const float* __restrict__ gamma, const float* __restrict__ beta,
                      const float* __restrict__ rmean, const float* __restrict__ rvar,
                      const float* __restrict__ Wc, const float* __restrict__ bc,
                      float* __restrict__ out, int n) {
    __shared__ float sW[640], sS[64], sB[64], sbc[16];
    int tid = threadIdx.x;
    for (int i = tid; i < 640; i += NBLK) sW[i] = Wc[i];
    if (tid < 64) {
        float sc = gamma[tid] * rsqrtf(rvar[tid] + 1e-5f);
        sS[tid] = sc;
        sB[tid] = beta[tid] - rmean[tid] * sc;
    }
    if (tid < 10) sbc[tid] = bc[tid];
    __syncthreads();

    int wid = tid >> 5, lane = tid & 31;
    int d = blockIdx.x * 8 + wid;
    if (d >= n) return;

    int hd = lane >> 3;
    float adst_l = (lane < 4) ? g_adst[d * 4 + lane] : 0.f;
    int start = g_off[d] + g_boff[d >> 8];
    int deg = g_cnt[d];

    float m0 = 0.f, m1 = 0.f, den = 0.f;
    for (int base = 0; base < deg; base += 32) {
        int nn = min(32, deg - base);
        int sv = (lane < nn) ? g_srcs[start + base + lane] : 0;
        for (int j = 0; j < nn; j++) {
            int s = __shfl_sync(0xffffffffu, sv, j);
            float w4 = 0.f;
            if (lane < 4) {
                float e = g_asrc[s * 4 + lane] + adst_l;
                w4 = __expf(leaky(e));
            }
            float w = __shfl_sync(0xffffffffu, w4, hd);
            float2 hv = ((const float2*)g_h)[s * 32 + lane];
            m0 += w * hv.x;
            m1 += w * hv.y;
            den += w;
        }
    }
    {   // self-loop
        float w4 = 0.f;
        if (lane < 4) {
            float e = g_asrc[d * 4 + lane] + adst_l;
            w4 = __expf(leaky(e));
        }
        float w = __shfl_sync(0xffffffffu, w4, hd);
        float2 hv = ((const float2*)g_h)[d * 32 + lane];
        m0 += w * hv.x;
        m1 += w * hv.y;
        den += w;
    }

    float inv = 1.f / (den + 1e-16f);
    float2 r = ((const float2*)g_acc)[d * 32 + lane];
    int c0 = 2 * lane;
    float h0 = r.x + m0 * inv;
    float h1 = r.y + m1 * inv;
    float hb0 = fmaxf(h0 * sS[c0] + sB[c0], 0.f);
    float hb1 = fmaxf(h1 * sS[c0 + 1] + sB[c0 + 1], 0.f);

    float lg[10];
#pragma unroll
    for (int c = 0; c < 10; c++)
        lg[c] = hb0 * sW[c0 * 10 + c] + hb1 * sW[(c0 + 1) * 10 + c];
#pragma unroll
    for (int off = 16; off; off >>= 1)
#pragma unroll
        for (int c = 0; c < 10; c++)
            lg[c] += __shfl_down_sync(0xffffffffu, lg[c], off);
    if (lane == 0) {
#pragma unroll
        for (int c = 0; c < 10; c++) out[d * 10 + c] = lg[c] + sbc[c];
    }
}

extern "C" void kernel_launch(void* const* d_in, const int* in_sizes, int n_in,
                              void* d_out, int out_size) {
    const float* x     = (const float*)d_in[0];
    const int*   ei    = (const int*)d_in[1];
    const float* Wg    = (const float*)d_in[2];
    const float* att_s = (const float*)d_in[3];
    const float* att_d = (const float*)d_in[4];
    const float* bg    = (const float*)d_in[5];
    const float* Wr    = (const float*)d_in[6];
    const float* br    = (const float*)d_in[7];
    const float* gamma = (const float*)d_in[8];
    const float* beta  = (const float*)d_in[9];
    const float* rmean = (const float*)d_in[10];
    const float* rvar  = (const float*)d_in[11];
    const float* Wc    = (const float*)d_in[12];
    const float* bc    = (const float*)d_in[13];
    float* out = (float*)d_out;

    int n = in_sizes[0] / 128;
    int E = in_sizes[1] / 2;

    int nodeB = (n + NBLK - 1) / NBLK;       // 196
    int edgeB = (E + NBLK - 1) / NBLK;
    int gemmB = (n + 31) / 32;

    k_zero<<<nodeB, NBLK>>>(n);
    k_gemm64<<<gemmB, NBLK>>>(x, Wg, bg, br, att_s, att_d, 0, n);
    k_gemm64<<<gemmB, NBLK>>>(x, Wr, bg, br, att_s, att_d, 1, n);
    k_hist<<<edgeB, NBLK>>>(ei, E);
    k_scan1<<<nodeB, NBLK>>>(n);
    k_scan2<<<1, 256>>>(nodeB);
    k_scatter<<<edgeB, NBLK>>>(ei, E);
    k_agg<<<(n + 7) / 8, NBLK>>>(gamma, beta, rmean, rvar, Wc, bc, out, n);
}

// round 3
// speedup vs baseline: 1.4410x; 1.0360x over previous
#include <cuda_runtime.h>

#define MAXN 50000
#define MAXE 1600000
#define NBLK 256

// ---------------- scratch (device globals; no allocation) ----------------
__device__ float  g_h[MAXN * 64];      // x @ W_gat
__device__ float  g_acc[MAXN * 64];    // x @ W_res + b_gat + b_res
__device__ float  g_asrc[MAXN * 4];
__device__ float  g_adst[MAXN * 4];
__device__ int    g_cnt[MAXN];         // in-degree
__device__ int    g_cur[MAXN];         // scatter cursors (init = row start)
__device__ int    g_off[MAXN];         // row starts (after k_fin)
__device__ int    g_bsum[256];
__device__ int    g_boff[256];
__device__ int    g_srcs[MAXE];        // CSR: src ids grouped by dst
__device__ float4 g_w4[MAXE];          // per-edge softmax weights (4 heads)

__device__ __forceinline__ float leaky(float v) { return v > 0.f ? v : 0.2f * v; }

// ---------------------------------------------------------------------------
// K0: zero histogram
// ---------------------------------------------------------------------------
__global__ void k_zero(int n) {
    int i = blockIdx.x * NBLK + threadIdx.x;
    if (i < n) g_cnt[i] = 0;
}

// ---------------------------------------------------------------------------
// K1: fused dual GEMM: g_h = x@Wg (+ attention logits), g_acc = x@Wr + biases.
// Dynamic smem: Wg[128*64] | Wr[128*64] | xs[32*128]  = 80KB.
// CTA: 32 nodes, 256 threads. lane tx -> 2 cols of each W; warp ty -> 4 nodes.
// ---------------------------------------------------------------------------
__global__ void k_gemm(const float* __restrict__ x,
                       const float* __restrict__ Wg, const float* __restrict__ Wr,
                       const float* __restrict__ b0, const float* __restrict__ b1,
                       const float* __restrict__ att_s, const float* __restrict__ att_d,
                       int n) {
    extern __shared__ float sm[];
    float* sWg = sm;               // 8192 floats
    float* sWr = sm + 8192;        // 8192 floats
    float* xs  = sm + 16384;       // 4096 floats
    int tid = threadIdx.x;
    for (int i = tid; i < 8192; i += NBLK) { sWg[i] = Wg[i]; sWr[i] = Wr[i]; }
    int base = blockIdx.x * 32;
    const float4* x4 = (const float4*)x;
    for (int i = tid; i < 32 * 32; i += NBLK) {
        int node = i >> 5, kk = i & 31;
        float4 v = make_float4(0.f, 0.f, 0.f, 0.f);
        if (base + node < n) v = x4[(base + node) * 32 + kk];
        ((float4*)xs)[i] = v;
    }
    __syncthreads();

    int tx = tid & 31;
    int ty = tid >> 5;
    float ag[4][2] = {}, ar[4][2] = {};
    const float* xp = xs + ty * 4 * 128;
#pragma unroll 4
    for (int k = 0; k < 128; k++) {
        float2 wg = ((const float2*)(sWg + k * 64))[tx];
        float2 wr = ((const float2*)(sWr + k * 64))[tx];
#pragma unroll
        for (int i = 0; i < 4; i++) {
            float xv = xp[i * 128 + k];
            ag[i][0] += xv * wg.x; ag[i][1] += xv * wg.y;
            ar[i][0] += xv * wr.x; ar[i][1] += xv * wr.y;
        }
    }

    float bias0 = b0[2 * tx] + b1[2 * tx];
    float bias1 = b0[2 * tx + 1] + b1[2 * tx + 1];
    float as0 = att_s[2 * tx], as1 = att_s[2 * tx + 1];
    float ad0 = att_d[2 * tx], ad1 = att_d[2 * tx + 1];
    int hd = tx >> 3;
#pragma unroll
    for (int i = 0; i < 4; i++) {
        int node = base + ty * 4 + i;
        float ps = ag[i][0] * as0 + ag[i][1] * as1;
        float pd = ag[i][0] * ad0 + ag[i][1] * ad1;
#pragma unroll
        for (int off = 4; off; off >>= 1) {
            ps += __shfl_xor_sync(0xffffffffu, ps, off);
            pd += __shfl_xor_sync(0xffffffffu, pd, off);
        }
        if (node < n) {
            ((float2*)(g_h + node * 64))[tx]   = make_float2(ag[i][0], ag[i][1]);
            ((float2*)(g_acc + node * 64))[tx] = make_float2(ar[i][0] + bias0, ar[i][1] + bias1);
            if ((tx & 7) == 0) {
                g_asrc[node * 4 + hd] = ps;
                g_adst[node * 4 + hd] = pd;
            }
        }
    }
}

// ---------------------------------------------------------------------------
// K2: degree histogram (4 edges per thread, int4 loads)
// ---------------------------------------------------------------------------
__global__ void k_hist(const int* __restrict__ ei, int E) {
    int i = (blockIdx.x * NBLK + threadIdx.x) * 4;
    if (i + 3 < E) {
        int4 d = *(const int4*)(ei + E + i);
        atomicAdd(&g_cnt[d.x], 1);
        atomicAdd(&g_cnt[d.y], 1);
        atomicAdd(&g_cnt[d.z], 1);
        atomicAdd(&g_cnt[d.w], 1);
    } else {
        for (int j = i; j < E; j++) atomicAdd(&g_cnt[ei[E + j]], 1);
    }
}

// K3a: per-block exclusive scan of cnt
__global__ void k_scan1(int n) {
    __shared__ int sh[NBLK];
    int t = threadIdx.x;
    int gid = blockIdx.x * NBLK + t;
    int v = (gid < n) ? g_cnt[gid] : 0;
    sh[t] = v;
    __syncthreads();
#pragma unroll
    for (int off = 1; off < NBLK; off <<= 1) {
        int xv = (t >= off) ? sh[t - off] : 0;
        __syncthreads();
        sh[t] += xv;
        __syncthreads();
    }
    if (gid < n) g_off[gid] = sh[t] - v;
    if (t == NBLK - 1) g_bsum[blockIdx.x] = sh[t];
}

// K3b: scan of block sums (single block)
__global__ void k_scan2(int nblocks) {
    __shared__ int sh[256];
    int t = threadIdx.x;
    int v = (t < nblocks) ? g_bsum[t] : 0;
    sh[t] = v;
    __syncthreads();
#pragma unroll
    for (int off = 1; off < 256; off <<= 1) {
        int xv = (t >= off) ? sh[t - off] : 0;
        __syncthreads();
        sh[t] += xv;
        __syncthreads();
    }
    g_boff[t] = sh[t] - v;
}

// K3c: absolute row starts + cursors
__global__ void k_fin(int n) {
    int i = blockIdx.x * NBLK + threadIdx.x;
    if (i < n) {
        int st = g_off[i] + g_boff[i >> 8];
        g_off[i] = st;
        g_cur[i] = st;
    }
}

// ---------------------------------------------------------------------------
// K4: scatter src ids into CSR order + precompute per-edge head weights
// ---------------------------------------------------------------------------
__global__ void k_scatter(const int* __restrict__ ei, int E) {
    int i = blockIdx.x * NBLK + threadIdx.x;
    if (i >= E) return;
    int s = ei[i], d = ei[E + i];
    int p = atomicAdd(&g_cur[d], 1);
    float4 as = ((const float4*)g_asrc)[s];
    float4 ad = ((const float4*)g_adst)[d];
    g_srcs[p] = s;
    g_w4[p] = make_float4(__expf(leaky(as.x + ad.x)),
                          __expf(leaky(as.y + ad.y)),
                          __expf(leaky(as.z + ad.z)),
                          __expf(leaky(as.w + ad.w)));
}

// ---------------------------------------------------------------------------
// K5: warp-per-destination gather aggregation (weights precomputed) fused with
// residual + BN + ReLU + classifier. Unnormalized softmax (logits are O(1)).
// Lane owns cols 2l,2l+1; head hd = l>>3.
// ---------------------------------------------------------------------------
__global__ void k_agg(const float* __restrict__ gamma, const float* __restrict__ beta,
                      const float* __restrict__ rmean, const float* __restrict__ rvar,
                      const float* __restrict__ Wc, const float* __restrict__ bc,
                      float* __restrict__ out, int n) {
    __shared__ float sW[640], sS[64], sB[64], sbc[16];
    int tid = threadIdx.x;
    for (int i = tid; i < 640; i += NBLK) sW[i] = Wc[i];
    if (tid < 64) {
        float sc = gamma[tid] * rsqrtf(rvar[tid] + 1e-5f);
        sS[tid] = sc;
        sB[tid] = beta[tid] - rmean[tid] * sc;
    }
    if (tid < 10) sbc[tid] = bc[tid];
    __syncthreads();

    int wid = tid >> 5, lane = tid & 31;
    int d = blockIdx.x * 8 + wid;
    if (d >= n) return;

    int hd = lane >> 3;
    int start = g_off[d];
    int deg = g_cnt[d];
    const float* wp = ((const float*)g_w4);
    const float2* hp = (const float2*)g_h;

    float m0 = 0.f, m1 = 0.f, den = 0.f;
    int p = start, rem = deg;
    for (; rem >= 4; rem -= 4, p += 4) {
        int s0 = g_srcs[p], s1 = g_srcs[p + 1], s2 = g_srcs[p + 2], s3 = g_srcs[p + 3];
        float w0 = wp[(p + 0) * 4 + hd];
        float w1 = wp[(p + 1) * 4 + hd];
        float w2 = wp[(p + 2) * 4 + hd];
        float w3 = wp[(p + 3) * 4 + hd];
        float2 h0 = hp[s0 * 32 + lane];
        float2 h1 = hp[s1 * 32 + lane];
        float2 h2 = hp[s2 * 32 + lane];
        float2 h3 = hp[s3 * 32 + lane];
        m0 += w0 * h0.x + w1 * h1.x;  m1 += w0 * h0.y + w1 * h1.y;
        m0 += w2 * h2.x + w3 * h3.x;  m1 += w2 * h2.y + w3 * h3.y;
        den += (w0 + w1) + (w2 + w3);
    }
    for (; rem > 0; rem--, p++) {
        int s = g_srcs[p];
        float w = wp[p * 4 + hd];
        float2 hv = hp[s * 32 + lane];
        m0 += w * hv.x; m1 += w * hv.y; den += w;
    }
    {   // self-loop
        float w = __expf(leaky(g_asrc[d * 4 + hd] + g_adst[d * 4 + hd]));
        float2 hv = hp[d * 32 + lane];
        m0 += w * hv.x; m1 += w * hv.y; den += w;
    }

    float inv = 1.f / (den + 1e-16f);
    float2 r = ((const float2*)g_acc)[d * 32 + lane];
    int c0 = 2 * lane;
    float h0 = r.x + m0 * inv;
    float h1 = r.y + m1 * inv;
    float hb0 = fmaxf(h0 * sS[c0] + sB[c0], 0.f);
    float hb1 = fmaxf(h1 * sS[c0 + 1] + sB[c0 + 1], 0.f);

    float lg[10];
#pragma unroll
    for (int c = 0; c < 10; c++)
        lg[c] = hb0 * sW[c0 * 10 + c] + hb1 * sW[(c0 + 1) * 10 + c];
#pragma unroll
    for (int off = 16; off; off >>= 1)
#pragma unroll
        for (int c = 0; c < 10; c++)
            lg[c] += __shfl_down_sync(0xffffffffu, lg[c], off);
    if (lane == 0) {
#pragma unroll
        for (int c = 0; c < 10; c++) out[d * 10 + c] = lg[c] + sbc[c];
    }
}

extern "C" void kernel_launch(void* const* d_in, const int* in_sizes, int n_in,
                              void* d_out, int out_size) {
    const float* x     = (const float*)d_in[0];
    const int*   ei    = (const int*)d_in[1];
    const float* Wg    = (const float*)d_in[2];
    const float* att_s = (const float*)d_in[3];
    const float* att_d = (const float*)d_in[4];
    const float* bg    = (const float*)d_in[5];
    const float* Wr    = (const float*)d_in[6];
    const float* br    = (const float*)d_in[7];
    const float* gamma = (const float*)d_in[8];
    const float* beta  = (const float*)d_in[9];
    const float* rmean = (const float*)d_in[10];
    const float* rvar  = (const float*)d_in[11];
    const float* Wc    = (const float*)d_in[12];
    const float* bc    = (const float*)d_in[13];
    float* out = (float*)d_out;

    int n = in_sizes[0] / 128;
    int E = in_sizes[1] / 2;

    int nodeB = (n + NBLK - 1) / NBLK;
    int edgeB = (E + NBLK - 1) / NBLK;
    int gemmB = (n + 31) / 32;

    static int smem_set = 0;
    if (!smem_set) {
        cudaFuncSetAttribute(k_gemm, cudaFuncAttributeMaxDynamicSharedMemorySize, 81920);
        smem_set = 1;
    }

    k_zero<<<nodeB, NBLK>>>(n);
    k_gemm<<<gemmB, NBLK, 81920>>>(x, Wg, Wr, bg, br, att_s, att_d, n);
    k_hist<<<(E / 4 + NBLK - 1) / NBLK, NBLK>>>(ei, E);
    k_scan1<<<nodeB, NBLK>>>(n);
    k_scan2<<<1, 256>>>(nodeB);
    k_fin<<<nodeB, NBLK>>>(n);
    k_scatter<<<edgeB, NBLK>>>(ei, E);
    k_agg<<<(n + 7) / 8, NBLK>>>(gamma, beta, rmean, rvar, Wc, bc, out, n);
}